// round 9
// baseline (speedup 1.0000x reference)
#include <cuda_runtime.h>
#include <cuda_fp16.h>
#include <cstdint>

#define HSZ    256
#define BATCH  512
#define TSTEPS 1024
#define G4     1024
#define FIN    10
#define PA     280   // smem pitch in halves (fits K=272; stride 560B is conflict-free for ldsm)
#define NB     128   // persistent CTAs (1 CTA/SM)
#define NGRP   4     // independent batch groups
#define GRPSZ  32    // CTAs per group

// ---------------- device scratch ----------------
__device__ __half g_whh0[G4 * HSZ];
__device__ __half g_wih1[G4 * HSZ];
__device__ __half g_whh1[G4 * HSZ];
__device__ __half g_advw1[HSZ * HSZ];
__device__ float  g_bias0[G4];
__device__ float  g_bias1[G4];
__device__ __half g_xTh[(size_t)TSTEPS * BATCH * 16];   // x transposed, fp16, padded 10->16
__device__ __half g_h1[2][BATCH * HSZ];
__device__ __half g_hs[(size_t)TSTEPS * BATCH * HSZ];   // h2 history == h2 state
__device__ float  g_scores[TSTEPS * BATCH];
__device__ unsigned g_barc[NGRP * 32];                  // 128B-spaced per group
__device__ unsigned g_barg[NGRP * 32];

// ---------------- math ----------------
__device__ __forceinline__ float tanh_ap(float x) {
    float y; asm("tanh.approx.f32 %0, %1;" : "=f"(y) : "f"(x)); return y;
}
__device__ __forceinline__ float sig_ap(float x) {
    return fmaf(tanh_ap(0.5f * x), 0.5f, 0.5f);
}

// ---------------- PTX helpers ----------------
__device__ __forceinline__ void ldsm_x4(uint32_t& r0, uint32_t& r1, uint32_t& r2, uint32_t& r3,
                                        uint32_t saddr) {
    asm volatile("ldmatrix.sync.aligned.m8n8.x4.shared.b16 {%0,%1,%2,%3}, [%4];"
                 : "=r"(r0), "=r"(r1), "=r"(r2), "=r"(r3) : "r"(saddr));
}
__device__ __forceinline__ void mma16816(float* c, uint32_t a0, uint32_t a1, uint32_t a2,
                                         uint32_t a3, uint32_t b0, uint32_t b1) {
    asm volatile(
        "mma.sync.aligned.m16n8k16.row.col.f32.f16.f16.f32 "
        "{%0,%1,%2,%3},{%4,%5,%6,%7},{%8,%9},{%0,%1,%2,%3};\n"
        : "+f"(c[0]), "+f"(c[1]), "+f"(c[2]), "+f"(c[3])
        : "r"(a0), "r"(a1), "r"(a2), "r"(a3), "r"(b0), "r"(b1));
}
__device__ __forceinline__ void cpasync16(uint32_t saddr, const void* g) {
    asm volatile("cp.async.cg.shared.global [%0], [%1], 16;" :: "r"(saddr), "l"(g));
}
__device__ __forceinline__ void cp_commit() { asm volatile("cp.async.commit_group;"); }
template <int N>
__device__ __forceinline__ void cp_wait() { asm volatile("cp.async.wait_group %0;" :: "n"(N)); }

// 16 cp.async/thread: [128 x 256] half tile (row stride HSZ) -> smem pitch PA
__device__ __forceinline__ void cp_tile(uint32_t at_s, const __half* __restrict__ src, int tid) {
#pragma unroll
    for (int k = 0; k < 16; k++) {
        int i = tid + k * 256;
        int r = i >> 5, c = (i & 31) * 8;
        cpasync16(at_s + (r * PA + c) * 2, src + r * HSZ + c);
    }
}

// group-local sense-reversing barrier (32 CTAs)
__device__ __forceinline__ void grp_barrier(int grp) {
    __syncthreads();
    if (threadIdx.x == 0) {
        __threadfence();   // publish our STGs
        volatile unsigned* genp = (volatile unsigned*)&g_barg[grp * 32];
        unsigned gen = *genp;
        if (atomicAdd(&g_barc[grp * 32], 1u) == GRPSZ - 1) {
            g_barc[grp * 32] = 0;
            __threadfence();
            *genp = gen + 1;
        } else {
            while (*genp == gen) { __nanosleep(32); }
        }
    }
    __syncthreads();
}

// ---------------- prologue ----------------
__global__ void k_prep(const float* __restrict__ whh0, const float* __restrict__ wih1,
                       const float* __restrict__ whh1, const float* __restrict__ advw1,
                       const float* __restrict__ bih0, const float* __restrict__ bhh0,
                       const float* __restrict__ bih1, const float* __restrict__ bhh1) {
    int i = blockIdx.x * blockDim.x + threadIdx.x;
    if (i < NGRP) { g_barc[i * 32] = 0; g_barg[i * 32] = 0; }
    if (i < G4 * HSZ) {
        g_whh0[i] = __float2half(whh0[i]);
        g_wih1[i] = __float2half(wih1[i]);
        g_whh1[i] = __float2half(whh1[i]);
    }
    if (i < HSZ * HSZ) g_advw1[i] = __float2half(advw1[i]);
    if (i < G4) { g_bias0[i] = bih0[i] + bhh0[i]; g_bias1[i] = bih1[i] + bhh1[i]; }
}

__global__ void k_xpose(const float* __restrict__ x) {
    int idx = blockIdx.x * blockDim.x + threadIdx.x;   // idx = b*T + t
    if (idx < BATCH * TSTEPS) {
        int b = idx >> 10, t = idx & 1023;
        const float* src = x + (size_t)idx * FIN;
        __half* dst = g_xTh + ((size_t)t * BATCH + b) * 16;
#pragma unroll
        for (int f = 0; f < FIN; f++) dst[f] = __float2half(src[f]);
#pragma unroll
        for (int f = FIN; f < 16; f++) dst[f] = __float2half(0.f);
    }
}

// ---------------- persistent LSTM kernel ----------------
__global__ void __launch_bounds__(256, 1) k_main(const float* __restrict__ wih0) {
    extern __shared__ char smraw[];
    __half* At1 = (__half*)smraw;               // h1|x tile 128 x PA (cols 256..271 = x(t+1))
    __half* At2 = At1 + 128 * PA;               // h2prev    128 x PA
    __half* Ws0 = At2 + 128 * PA;               // [whh0|wih0] slice 32 x PA
    __half* Ws1 = Ws0 + 32 * PA;                // wih1 slice
    __half* Ws2 = Ws1 + 32 * PA;                // whh1 slice
    __half* xsm = Ws2 + 32 * PA;                // 128 x 16 (step-0 x)
    float*  wxs = (float*)(xsm + 128 * 16);     // 32 x 10 (step-0 wih0)
    float*  b0s = wxs + 32 * FIN;               // 32
    float*  b1s = b0s + 32;                     // 32

    int tid = threadIdx.x;
    int grp = blockIdx.x >> 5;
    int m0 = grp * 128;                          // batch tile
    int hbase = (blockIdx.x & 31) * 8;           // h-slice

    // one-time weight staging (cols 0..255)
    for (int i = tid; i < 32 * 32; i += 256) {
        int r = i >> 5, c = (i & 31) * 8;
        int s = r >> 3, n = r & 7;
        int grow = (s * 256 + hbase + n) * HSZ + c;
        *(uint4*)(Ws0 + r * PA + c) = *(const uint4*)(g_whh0 + grow);
        *(uint4*)(Ws1 + r * PA + c) = *(const uint4*)(g_wih1 + grow);
        *(uint4*)(Ws2 + r * PA + c) = *(const uint4*)(g_whh1 + grow);
    }
    // Ws0 cols 256..271 = wih0 slice (10 cols) + zero pad
    for (int i = tid; i < 32 * 16; i += 256) {
        int r = i >> 4, c = i & 15;
        int s = r >> 3, n = r & 7;
        Ws0[r * PA + 256 + c] =
            (c < FIN) ? __float2half(wih0[(s * 256 + hbase + n) * FIN + c]) : __half(__float2half(0.f));
    }
    for (int i = tid; i < 32 * FIN; i += 256) {
        int r = i / FIN, f = i - r * FIN;
        int s = r >> 3, n = r & 7;
        wxs[i] = wih0[(s * 256 + hbase + n) * FIN + f];
    }
    if (tid < 32) {
        int s = tid >> 3, n = tid & 7;
        b0s[tid] = g_bias0[s * 256 + hbase + n];
        b1s[tid] = g_bias1[s * 256 + hbase + n];
    }

    int w = tid >> 5, lane = tid & 31, g = lane >> 2, tq = lane & 3;
    int quad = lane >> 3, qi = lane & 7;
    int rl0 = w * 16 + g;
    int colb = hbase + 2 * tq;

    uint32_t a_off = ((uint32_t)(w * 16 + (quad & 1) * 8 + qi) * PA + (quad >> 1) * 8) * 2;
    uint32_t at1_s = (uint32_t)__cvta_generic_to_shared(At1);
    uint32_t at2_s = (uint32_t)__cvta_generic_to_shared(At2);
    uint32_t b_off = ((uint32_t)((quad >> 1) * 8 + qi) * PA + (quad & 1) * 8) * 2;
    uint32_t ws0_s = (uint32_t)__cvta_generic_to_shared(Ws0) + b_off;
    uint32_t ws1_s = (uint32_t)__cvta_generic_to_shared(Ws1) + b_off;
    uint32_t ws2_s = (uint32_t)__cvta_generic_to_shared(Ws2) + b_off;
    const uint32_t PSTRIDE = 16 * PA * 2;

    float c1v[4] = {0.f, 0.f, 0.f, 0.f};
    float c2v[4] = {0.f, 0.f, 0.f, 0.f};

    // ---- A(0): h1(0) = lstm0(x0, 0, 0), scalar path ----
    for (int i = tid; i < 128 * 2; i += 256) {   // 128 rows x 16 halves, 8-half chunks
        int r = i >> 1, c = (i & 1) * 8;
        *(uint4*)(xsm + r * 16 + c) = *(const uint4*)(g_xTh + ((size_t)0 * BATCH + m0 + r) * 16 + c);
    }
    __syncthreads();
    {
        float hv[4];
#pragma unroll
        for (int j = 0; j < 4; j++) {
            int rl = rl0 + ((j & 2) ? 8 : 0);
            int cl = 2 * tq + (j & 1);
            float p[4];
#pragma unroll
            for (int s = 0; s < 4; s++) {
                float acc = b0s[s * 8 + cl];
#pragma unroll
                for (int f = 0; f < FIN; f++)
                    acc += __half2float(xsm[rl * 16 + f]) * wxs[(s * 8 + cl) * FIN + f];
                p[s] = acc;
            }
            float ig = sig_ap(p[0]), fg = sig_ap(p[1]);
            float gg = tanh_ap(p[2]), og = sig_ap(p[3]);
            float c = fg * c1v[j] + ig * gg;
            c1v[j] = c;
            hv[j] = og * tanh_ap(c);
        }
        __half2* dst = (__half2*)(g_h1[0]);
        dst[((m0 + rl0) * HSZ + colb) >> 1]     = __floats2half2_rn(hv[0], hv[1]);
        dst[((m0 + rl0 + 8) * HSZ + colb) >> 1] = __floats2half2_rn(hv[2], hv[3]);
    }
    grp_barrier(grp);

    // ---- main loop: phase t = [ B(t) ; A(t+1) ] ----
    for (int t = 0; t < TSTEPS; t++) {
        const __half* h1cur  = g_h1[t & 1];
        const __half* h2prev = g_hs + (size_t)((t > 0) ? (t - 1) : 0) * BATCH * HSZ;

        // group 0: h1 tile (needed first)
        cp_tile(at1_s, h1cur + m0 * HSZ, tid);
        cp_commit();
        // group 1: x(t+1) into At1 cols 256.. + h2prev tile
        if (t + 1 < TSTEPS) {
            int r = tid >> 1, c = (tid & 1) * 8;
            cpasync16(at1_s + (r * PA + 256 + c) * 2,
                      g_xTh + ((size_t)(t + 1) * BATCH + m0 + r) * 16 + c);
        }
        if (t > 0) cp_tile(at2_s, h2prev + m0 * HSZ, tid);
        cp_commit();

        cp_wait<1>();
        __syncthreads();

        float accA[4][4] = {};   // h1 @ whh0^T (+ x @ wih0^T)  -> layer0, t+1
        float accB[4][4] = {};   // h1 @ wih1^T + h2prev @ whh1^T -> layer1, t
#pragma unroll
        for (int kc = 0; kc < HSZ; kc += 16) {
            uint32_t a0, a1, a2, a3, b0, b1, b2, b3;
            ldsm_x4(a0, a1, a2, a3, at1_s + a_off + kc * 2);
#pragma unroll
            for (int p = 0; p < 2; p++) {
                ldsm_x4(b0, b1, b2, b3, ws0_s + p * PSTRIDE + kc * 2);
                mma16816(accA[2 * p],     a0, a1, a2, a3, b0, b1);
                mma16816(accA[2 * p + 1], a0, a1, a2, a3, b2, b3);
                ldsm_x4(b0, b1, b2, b3, ws1_s + p * PSTRIDE + kc * 2);
                mma16816(accB[2 * p],     a0, a1, a2, a3, b0, b1);
                mma16816(accB[2 * p + 1], a0, a1, a2, a3, b2, b3);
            }
        }
        cp_wait<0>();
        __syncthreads();
        // x chunk (kc = 256) -> accA only
        if (t + 1 < TSTEPS) {
            uint32_t a0, a1, a2, a3, b0, b1, b2, b3;
            ldsm_x4(a0, a1, a2, a3, at1_s + a_off + 256 * 2);
#pragma unroll
            for (int p = 0; p < 2; p++) {
                ldsm_x4(b0, b1, b2, b3, ws0_s + p * PSTRIDE + 256 * 2);
                mma16816(accA[2 * p],     a0, a1, a2, a3, b0, b1);
                mma16816(accA[2 * p + 1], a0, a1, a2, a3, b2, b3);
            }
        }
        // pass 2: h2prev @ whh1^T
        if (t > 0) {
#pragma unroll
            for (int kc = 0; kc < HSZ; kc += 16) {
                uint32_t a0, a1, a2, a3, b0, b1, b2, b3;
                ldsm_x4(a0, a1, a2, a3, at2_s + a_off + kc * 2);
#pragma unroll
                for (int p = 0; p < 2; p++) {
                    ldsm_x4(b0, b1, b2, b3, ws2_s + p * PSTRIDE + kc * 2);
                    mma16816(accB[2 * p],     a0, a1, a2, a3, b0, b1);
                    mma16816(accB[2 * p + 1], a0, a1, a2, a3, b2, b3);
                }
            }
        }

        // epilogue B: h2(t), c2
        {
            float hv[4];
#pragma unroll
            for (int j = 0; j < 4; j++) {
                int cl = 2 * tq + (j & 1);
                float p[4];
#pragma unroll
                for (int s = 0; s < 4; s++) p[s] = accB[s][j] + b1s[s * 8 + cl];
                float ig = sig_ap(p[0]), fg = sig_ap(p[1]);
                float gg = tanh_ap(p[2]), og = sig_ap(p[3]);
                float c = fg * c2v[j] + ig * gg;
                c2v[j] = c;
                hv[j] = og * tanh_ap(c);
            }
            __half2* dst = (__half2*)(g_hs + (size_t)t * BATCH * HSZ);
            dst[((m0 + rl0) * HSZ + colb) >> 1]     = __floats2half2_rn(hv[0], hv[1]);
            dst[((m0 + rl0 + 8) * HSZ + colb) >> 1] = __floats2half2_rn(hv[2], hv[3]);
        }
        // epilogue A: h1(t+1), c1  (x-projection already in accA)
        if (t + 1 < TSTEPS) {
            float hv[4];
#pragma unroll
            for (int j = 0; j < 4; j++) {
                int cl = 2 * tq + (j & 1);
                float p[4];
#pragma unroll
                for (int s = 0; s < 4; s++) p[s] = accA[s][j] + b0s[s * 8 + cl];
                float ig = sig_ap(p[0]), fg = sig_ap(p[1]);
                float gg = tanh_ap(p[2]), og = sig_ap(p[3]);
                float c = fg * c1v[j] + ig * gg;
                c1v[j] = c;
                hv[j] = og * tanh_ap(c);
            }
            __half2* dst = (__half2*)(g_h1[(t + 1) & 1]);
            dst[((m0 + rl0) * HSZ + colb) >> 1]     = __floats2half2_rn(hv[0], hv[1]);
            dst[((m0 + rl0 + 8) * HSZ + colb) >> 1] = __floats2half2_rn(hv[2], hv[3]);
        }
        grp_barrier(grp);
    }
}

// ---------------- advantage head (ldmatrix path) ----------------
__global__ void __launch_bounds__(256) k_head(const float* __restrict__ advb1,
                                              const float* __restrict__ advw2) {
    extern __shared__ char smraw[];
    __half* At  = (__half*)smraw;               // 128 x PA
    __half* Wc  = At + 128 * PA;                // 32 x PA
    float*  b1s = (float*)(Wc + 32 * PA);       // 256
    float*  w2s = b1s + HSZ;                    // 256

    int tid = threadIdx.x;
    size_t rowbase = (size_t)blockIdx.x * 128;

    for (int i = tid; i < 128 * 32; i += 256) {
        int r = i >> 5, c = (i & 31) * 8;
        *(uint4*)(At + r * PA + c) = *(const uint4*)(g_hs + rowbase * HSZ + r * HSZ + c);
    }
    if (tid < HSZ) { b1s[tid] = advb1[tid]; w2s[tid] = advw2[tid]; }

    int w = tid >> 5, lane = tid & 31, g = lane >> 2, tq = lane & 3;
    int quad = lane >> 3, qi = lane & 7;
    uint32_t a_off = ((uint32_t)(w * 16 + (quad & 1) * 8 + qi) * PA + (quad >> 1) * 8) * 2;
    uint32_t at_s = (uint32_t)__cvta_generic_to_shared(At);
    uint32_t b_off = ((uint32_t)((quad >> 1) * 8 + qi) * PA + (quad & 1) * 8) * 2;
    uint32_t wc_s = (uint32_t)__cvta_generic_to_shared(Wc) + b_off;
    const uint32_t PSTRIDE = 16 * PA * 2;

    float ps0 = 0.f, ps1 = 0.f;

    for (int ch = 0; ch < 8; ch++) {
        int c0 = ch * 32;
        __syncthreads();
        for (int i = tid; i < 32 * 32; i += 256) {
            int r = i >> 5, c = (i & 31) * 8;
            *(uint4*)(Wc + r * PA + c) = *(const uint4*)(g_advw1 + (c0 + r) * HSZ + c);
        }
        __syncthreads();
        float acc[4][4] = {};
#pragma unroll
        for (int kc = 0; kc < HSZ; kc += 16) {
            uint32_t a0, a1, a2, a3, b0, b1, b2, b3;
            ldsm_x4(a0, a1, a2, a3, at_s + a_off + kc * 2);
#pragma unroll
            for (int p = 0; p < 2; p++) {
                ldsm_x4(b0, b1, b2, b3, wc_s + p * PSTRIDE + kc * 2);
                mma16816(acc[2 * p],     a0, a1, a2, a3, b0, b1);
                mma16816(acc[2 * p + 1], a0, a1, a2, a3, b2, b3);
            }
        }
#pragma unroll
        for (int nt = 0; nt < 4; nt++) {
#pragma unroll
            for (int j = 0; j < 4; j++) {
                int col = c0 + nt * 8 + 2 * tq + (j & 1);
                float v = acc[nt][j] + b1s[col];
                v = fmaxf(v, 0.f) * w2s[col];
                if (j & 2) ps1 += v; else ps0 += v;
            }
        }
    }
    ps0 += __shfl_xor_sync(0xffffffffu, ps0, 1);
    ps0 += __shfl_xor_sync(0xffffffffu, ps0, 2);
    ps1 += __shfl_xor_sync(0xffffffffu, ps1, 1);
    ps1 += __shfl_xor_sync(0xffffffffu, ps1, 2);
    int g8 = w * 16 + g;
    if (tq == 0) {
        g_scores[rowbase + g8]     = ps0;   // +b2 omitted: softmax-invariant
        g_scores[rowbase + g8 + 8] = ps1;
    }
}

// ---------------- softmax over contiguous 1024-blocks ----------------
__global__ void __launch_bounds__(256) k_softmax(float* __restrict__ out) {
    __shared__ float red[256];
    int row = blockIdx.x, tid = threadIdx.x;
    const float* src = g_scores + row * 1024;

    float m = -1e30f;
    for (int j = tid; j < 1024; j += 256) m = fmaxf(m, src[j]);
    red[tid] = m; __syncthreads();
    for (int s = 128; s > 0; s >>= 1) { if (tid < s) red[tid] = fmaxf(red[tid], red[tid + s]); __syncthreads(); }
    m = red[0]; __syncthreads();

    float sum = 0.f;
    float e[4];
#pragma unroll
    for (int k = 0; k < 4; k++) { e[k] = expf(src[tid + k * 256] - m); sum += e[k]; }
    red[tid] = sum; __syncthreads();
    for (int s = 128; s > 0; s >>= 1) { if (tid < s) red[tid] += red[tid + s]; __syncthreads(); }
    float inv = 1.f / red[0];
#pragma unroll
    for (int k = 0; k < 4; k++) out[row * 1024 + tid + k * 256] = e[k] * inv;
}

// ---------------- launch ----------------
extern "C" void kernel_launch(void* const* d_in, const int* in_sizes, int n_in,
                              void* d_out, int out_size) {
    (void)in_sizes; (void)n_in; (void)out_size;
    const float* x     = (const float*)d_in[0];
    const float* wih0  = (const float*)d_in[1];
    const float* whh0  = (const float*)d_in[2];
    const float* bih0  = (const float*)d_in[3];
    const float* bhh0  = (const float*)d_in[4];
    const float* wih1  = (const float*)d_in[5];
    const float* whh1  = (const float*)d_in[6];
    const float* bih1  = (const float*)d_in[7];
    const float* bhh1  = (const float*)d_in[8];
    const float* advw1 = (const float*)d_in[9];
    const float* advb1 = (const float*)d_in[10];
    const float* advw2 = (const float*)d_in[11];
    float* out = (float*)d_out;

    const int SMM = (2 * 128 + 3 * 32) * PA * 2 + 128 * 16 * 2 + (32 * FIN + 64) * 4;
    const int SMH = (128 + 32) * PA * 2 + 2 * HSZ * 4;
    cudaFuncSetAttribute(k_main, cudaFuncAttributeMaxDynamicSharedMemorySize, SMM);
    cudaFuncSetAttribute(k_head, cudaFuncAttributeMaxDynamicSharedMemorySize, SMH);

    k_prep<<<1024, 256>>>(whh0, wih1, whh1, advw1, bih0, bhh0, bih1, bhh1);
    k_xpose<<<2048, 256>>>(x);
    k_main<<<NB, 256, SMM>>>(wih0);
    k_head<<<4096, 256, SMH>>>(advb1, advw2);
    k_softmax<<<512, 256>>>(out);
}

// round 15
// speedup vs baseline: 1.0040x; 1.0040x over previous
#include <cuda_runtime.h>
#include <cuda_fp16.h>
#include <cstdint>

#define HSZ    256
#define BATCH  512
#define TSTEPS 1024
#define G4     1024
#define FIN    10
#define PA     280   // k_main smem pitch in halves
#define PAH    264   // k_head smem pitch in halves
#define NB     128   // persistent CTAs (1 CTA/SM)
#define NGRP   4
#define GRPSZ  32

// ---------------- device scratch ----------------
__device__ __half g_whh0[G4 * HSZ];
__device__ __half g_wih1[G4 * HSZ];
__device__ __half g_whh1[G4 * HSZ];
__device__ __half g_advw1[HSZ * HSZ];
__device__ float  g_bias0[G4];
__device__ float  g_bias1[G4];
__device__ __half g_xTh[(size_t)TSTEPS * BATCH * 16];   // x transposed, fp16, padded 10->16
__device__ __half g_h1[2][BATCH * HSZ];
__device__ __half g_hs[(size_t)TSTEPS * BATCH * HSZ];   // h2 history == h2 state
__device__ float  g_scores[TSTEPS * BATCH];
__device__ unsigned g_barc[NGRP * 32];
__device__ unsigned g_barg[NGRP * 32];

// ---------------- math ----------------
__device__ __forceinline__ float tanh_ap(float x) {
    float y; asm("tanh.approx.f32 %0, %1;" : "=f"(y) : "f"(x)); return y;
}
__device__ __forceinline__ float sig_ap(float x) {
    return fmaf(tanh_ap(0.5f * x), 0.5f, 0.5f);
}

// ---------------- PTX helpers ----------------
__device__ __forceinline__ void ldsm_x4(uint32_t& r0, uint32_t& r1, uint32_t& r2, uint32_t& r3,
                                        uint32_t saddr) {
    asm volatile("ldmatrix.sync.aligned.m8n8.x4.shared.b16 {%0,%1,%2,%3}, [%4];"
                 : "=r"(r0), "=r"(r1), "=r"(r2), "=r"(r3) : "r"(saddr));
}
__device__ __forceinline__ void mma16816(float* c, uint32_t a0, uint32_t a1, uint32_t a2,
                                         uint32_t a3, uint32_t b0, uint32_t b1) {
    asm volatile(
        "mma.sync.aligned.m16n8k16.row.col.f32.f16.f16.f32 "
        "{%0,%1,%2,%3},{%4,%5,%6,%7},{%8,%9},{%0,%1,%2,%3};\n"
        : "+f"(c[0]), "+f"(c[1]), "+f"(c[2]), "+f"(c[3])
        : "r"(a0), "r"(a1), "r"(a2), "r"(a3), "r"(b0), "r"(b1));
}
__device__ __forceinline__ void cpasync16(uint32_t saddr, const void* g) {
    asm volatile("cp.async.cg.shared.global [%0], [%1], 16;" :: "r"(saddr), "l"(g));
}
__device__ __forceinline__ void cp_commit() { asm volatile("cp.async.commit_group;"); }
template <int N>
__device__ __forceinline__ void cp_wait() { asm volatile("cp.async.wait_group %0;" :: "n"(N)); }

// stage h1 K-half: 8 cp/thread covers all 128 rows x 128 cols (half = 0 or 1)
__device__ __forceinline__ void cp_tile_half(uint32_t at_s, const __half* __restrict__ src,
                                             int tid, int half) {
#pragma unroll
    for (int k = 0; k < 8; k++) {
        int i = tid + (k << 8);
        int r = i >> 4, c = half * 128 + (i & 15) * 8;
        cpasync16(at_s + (r * PA + c) * 2, src + r * HSZ + c);
    }
}
// full [128 x 256] tile: 16 cp/thread
__device__ __forceinline__ void cp_tile(uint32_t at_s, const __half* __restrict__ src, int tid) {
#pragma unroll
    for (int k = 0; k < 16; k++) {
        int i = tid + (k << 8);
        int r = i >> 5, c = (i & 31) * 8;
        cpasync16(at_s + (r * PA + c) * 2, src + r * HSZ + c);
    }
}

// group-local sense-reversing barrier (32 CTAs)
__device__ __forceinline__ void grp_barrier(int grp) {
    __syncthreads();
    if (threadIdx.x == 0) {
        __threadfence();
        volatile unsigned* genp = (volatile unsigned*)&g_barg[grp * 32];
        unsigned gen = *genp;
        if (atomicAdd(&g_barc[grp * 32], 1u) == GRPSZ - 1) {
            g_barc[grp * 32] = 0;
            __threadfence();
            *genp = gen + 1;
        } else {
            while (*genp == gen) { __nanosleep(32); }
        }
    }
    __syncthreads();
}

// ---------------- prologue ----------------
__global__ void k_prep(const float* __restrict__ whh0, const float* __restrict__ wih1,
                       const float* __restrict__ whh1, const float* __restrict__ advw1,
                       const float* __restrict__ bih0, const float* __restrict__ bhh0,
                       const float* __restrict__ bih1, const float* __restrict__ bhh1) {
    int i = blockIdx.x * blockDim.x + threadIdx.x;
    if (i < NGRP) { g_barc[i * 32] = 0; g_barg[i * 32] = 0; }
    if (i < G4 * HSZ) {
        g_whh0[i] = __float2half(whh0[i]);
        g_wih1[i] = __float2half(wih1[i]);
        g_whh1[i] = __float2half(whh1[i]);
    }
    if (i < HSZ * HSZ) g_advw1[i] = __float2half(advw1[i]);
    if (i < G4) { g_bias0[i] = bih0[i] + bhh0[i]; g_bias1[i] = bih1[i] + bhh1[i]; }
}

__global__ void k_xpose(const float* __restrict__ x) {
    int idx = blockIdx.x * blockDim.x + threadIdx.x;   // idx = b*T + t
    if (idx < BATCH * TSTEPS) {
        int b = idx >> 10, t = idx & 1023;
        const float* src = x + (size_t)idx * FIN;
        __half* dst = g_xTh + ((size_t)t * BATCH + b) * 16;
#pragma unroll
        for (int f = 0; f < FIN; f++) dst[f] = __float2half(src[f]);
#pragma unroll
        for (int f = FIN; f < 16; f++) dst[f] = __float2half(0.f);
    }
}

// ---------------- persistent LSTM kernel ----------------
__global__ void __launch_bounds__(256, 1) k_main(const float* __restrict__ wih0) {
    extern __shared__ char smraw[];
    __half* At1 = (__half*)smraw;               // h1|x tile 128 x PA (cols 256..271 = x(t+1))
    __half* At2 = At1 + 128 * PA;               // h2prev    128 x PA
    __half* Ws0 = At2 + 128 * PA;               // [whh0|wih0] slice 32 x PA
    __half* Ws1 = Ws0 + 32 * PA;                // wih1 slice
    __half* Ws2 = Ws1 + 32 * PA;                // whh1 slice
    __half* xsm = Ws2 + 32 * PA;                // 128 x 16 (step-0 x)
    float*  wxs = (float*)(xsm + 128 * 16);     // 32 x 10 (step-0 wih0)
    float*  b0s = wxs + 32 * FIN;               // 32
    float*  b1s = b0s + 32;                     // 32

    int tid = threadIdx.x;
    int grp = blockIdx.x >> 5;
    int m0 = grp * 128;
    int hbase = (blockIdx.x & 31) * 8;

    // one-time weight staging (cols 0..255)
    for (int i = tid; i < 32 * 32; i += 256) {
        int r = i >> 5, c = (i & 31) * 8;
        int s = r >> 3, n = r & 7;
        int grow = (s * 256 + hbase + n) * HSZ + c;
        *(uint4*)(Ws0 + r * PA + c) = *(const uint4*)(g_whh0 + grow);
        *(uint4*)(Ws1 + r * PA + c) = *(const uint4*)(g_wih1 + grow);
        *(uint4*)(Ws2 + r * PA + c) = *(const uint4*)(g_whh1 + grow);
    }
    // Ws0 cols 256..271 = wih0 slice + zero pad
    for (int i = tid; i < 32 * 16; i += 256) {
        int r = i >> 4, c = i & 15;
        int s = r >> 3, n = r & 7;
        Ws0[r * PA + 256 + c] =
            (c < FIN) ? __float2half(wih0[(s * 256 + hbase + n) * FIN + c]) : __half(__float2half(0.f));
    }
    for (int i = tid; i < 32 * FIN; i += 256) {
        int r = i / FIN, f = i - r * FIN;
        int s = r >> 3, n = r & 7;
        wxs[i] = wih0[(s * 256 + hbase + n) * FIN + f];
    }
    if (tid < 32) {
        int s = tid >> 3, n = tid & 7;
        b0s[tid] = g_bias0[s * 256 + hbase + n];
        b1s[tid] = g_bias1[s * 256 + hbase + n];
    }

    int w = tid >> 5, lane = tid & 31, g = lane >> 2, tq = lane & 3;
    int quad = lane >> 3, qi = lane & 7;
    int rl0 = w * 16 + g;
    int colb = hbase + 2 * tq;

    uint32_t a_off = ((uint32_t)(w * 16 + (quad & 1) * 8 + qi) * PA + (quad >> 1) * 8) * 2;
    uint32_t at1_s = (uint32_t)__cvta_generic_to_shared(At1);
    uint32_t at2_s = (uint32_t)__cvta_generic_to_shared(At2);
    uint32_t b_off = ((uint32_t)((quad >> 1) * 8 + qi) * PA + (quad & 1) * 8) * 2;
    uint32_t ws0_s = (uint32_t)__cvta_generic_to_shared(Ws0) + b_off;
    uint32_t ws1_s = (uint32_t)__cvta_generic_to_shared(Ws1) + b_off;
    uint32_t ws2_s = (uint32_t)__cvta_generic_to_shared(Ws2) + b_off;
    const uint32_t PSTRIDE = 16 * PA * 2;

    float c1v[4] = {0.f, 0.f, 0.f, 0.f};
    float c2v[4] = {0.f, 0.f, 0.f, 0.f};

    // ---- A(0): h1(0) = lstm0(x0, 0, 0), scalar path ----
    for (int i = tid; i < 128 * 2; i += 256) {
        int r = i >> 1, c = (i & 1) * 8;
        *(uint4*)(xsm + r * 16 + c) = *(const uint4*)(g_xTh + ((size_t)0 * BATCH + m0 + r) * 16 + c);
    }
    __syncthreads();
    {
        float hv[4];
#pragma unroll
        for (int j = 0; j < 4; j++) {
            int rl = rl0 + ((j & 2) ? 8 : 0);
            int cl = 2 * tq + (j & 1);
            float p[4];
#pragma unroll
            for (int s = 0; s < 4; s++) {
                float acc = b0s[s * 8 + cl];
#pragma unroll
                for (int f = 0; f < FIN; f++)
                    acc += __half2float(xsm[rl * 16 + f]) * wxs[(s * 8 + cl) * FIN + f];
                p[s] = acc;
            }
            float ig = sig_ap(p[0]), fg = sig_ap(p[1]);
            float gg = tanh_ap(p[2]), og = sig_ap(p[3]);
            float c = fg * c1v[j] + ig * gg;
            c1v[j] = c;
            hv[j] = og * tanh_ap(c);
        }
        __half2* dst = (__half2*)(g_h1[0]);
        dst[((m0 + rl0) * HSZ + colb) >> 1]     = __floats2half2_rn(hv[0], hv[1]);
        dst[((m0 + rl0 + 8) * HSZ + colb) >> 1] = __floats2half2_rn(hv[2], hv[3]);
    }
    grp_barrier(grp);

    // ---- main loop: phase t = [ B(t) ; A(t+1) ] with split-K pipelined staging ----
    for (int t = 0; t < TSTEPS; t++) {
        const __half* h1cur = g_h1[t & 1];

        // g0: h1 K-half 0 (cols 0..127)
        cp_tile_half(at1_s, h1cur + m0 * HSZ, tid, 0);
        cp_commit();
        // g1: h1 K-half 1 (cols 128..255) + x(t+1)
        cp_tile_half(at1_s, h1cur + m0 * HSZ, tid, 1);
        if (t + 1 < TSTEPS) {
            int r = tid >> 1, c8 = (tid & 1) * 8;
            cpasync16(at1_s + (r * PA + 256 + c8) * 2,
                      g_xTh + ((size_t)(t + 1) * BATCH + m0 + r) * 16 + c8);
        }
        cp_commit();
        // g2: h2prev tile
        if (t > 0)
            cp_tile(at2_s, g_hs + (size_t)(t - 1) * BATCH * HSZ + m0 * HSZ, tid);
        cp_commit();

        float accA[4][4] = {};   // h1 @ whh0^T (+ x @ wih0^T)  -> layer0, t+1
        float accB[4][4] = {};   // h1 @ wih1^T + h2prev @ whh1^T -> layer1, t

        // segment 1: K-half 0 (kc 0..112)
        cp_wait<2>();
        __syncthreads();
#pragma unroll
        for (int kc = 0; kc < 128; kc += 16) {
            uint32_t a0, a1, a2, a3, b0, b1, b2, b3;
            ldsm_x4(a0, a1, a2, a3, at1_s + a_off + kc * 2);
#pragma unroll
            for (int p = 0; p < 2; p++) {
                ldsm_x4(b0, b1, b2, b3, ws0_s + p * PSTRIDE + kc * 2);
                mma16816(accA[2 * p],     a0, a1, a2, a3, b0, b1);
                mma16816(accA[2 * p + 1], a0, a1, a2, a3, b2, b3);
                ldsm_x4(b0, b1, b2, b3, ws1_s + p * PSTRIDE + kc * 2);
                mma16816(accB[2 * p],     a0, a1, a2, a3, b0, b1);
                mma16816(accB[2 * p + 1], a0, a1, a2, a3, b2, b3);
            }
        }
        // segment 2: K-half 1 (kc 128..240) + x chunk (kc 256, accA only)
        cp_wait<1>();
        __syncthreads();
#pragma unroll
        for (int kc = 128; kc < 256; kc += 16) {
            uint32_t a0, a1, a2, a3, b0, b1, b2, b3;
            ldsm_x4(a0, a1, a2, a3, at1_s + a_off + kc * 2);
#pragma unroll
            for (int p = 0; p < 2; p++) {
                ldsm_x4(b0, b1, b2, b3, ws0_s + p * PSTRIDE + kc * 2);
                mma16816(accA[2 * p],     a0, a1, a2, a3, b0, b1);
                mma16816(accA[2 * p + 1], a0, a1, a2, a3, b2, b3);
                ldsm_x4(b0, b1, b2, b3, ws1_s + p * PSTRIDE + kc * 2);
                mma16816(accB[2 * p],     a0, a1, a2, a3, b0, b1);
                mma16816(accB[2 * p + 1], a0, a1, a2, a3, b2, b3);
            }
        }
        if (t + 1 < TSTEPS) {
            uint32_t a0, a1, a2, a3, b0, b1, b2, b3;
            ldsm_x4(a0, a1, a2, a3, at1_s + a_off + 256 * 2);
#pragma unroll
            for (int p = 0; p < 2; p++) {
                ldsm_x4(b0, b1, b2, b3, ws0_s + p * PSTRIDE + 256 * 2);
                mma16816(accA[2 * p],     a0, a1, a2, a3, b0, b1);
                mma16816(accA[2 * p + 1], a0, a1, a2, a3, b2, b3);
            }
        }
        // segment 3: h2prev @ whh1^T
        cp_wait<0>();
        __syncthreads();
        if (t > 0) {
#pragma unroll
            for (int kc = 0; kc < 256; kc += 16) {
                uint32_t a0, a1, a2, a3, b0, b1, b2, b3;
                ldsm_x4(a0, a1, a2, a3, at2_s + a_off + kc * 2);
#pragma unroll
                for (int p = 0; p < 2; p++) {
                    ldsm_x4(b0, b1, b2, b3, ws2_s + p * PSTRIDE + kc * 2);
                    mma16816(accB[2 * p],     a0, a1, a2, a3, b0, b1);
                    mma16816(accB[2 * p + 1], a0, a1, a2, a3, b2, b3);
                }
            }
        }

        // epilogue B: h2(t), c2
        {
            float hv[4];
#pragma unroll
            for (int j = 0; j < 4; j++) {
                int cl = 2 * tq + (j & 1);
                float p[4];
#pragma unroll
                for (int s = 0; s < 4; s++) p[s] = accB[s][j] + b1s[s * 8 + cl];
                float ig = sig_ap(p[0]), fg = sig_ap(p[1]);
                float gg = tanh_ap(p[2]), og = sig_ap(p[3]);
                float c = fg * c2v[j] + ig * gg;
                c2v[j] = c;
                hv[j] = og * tanh_ap(c);
            }
            __half2* dst = (__half2*)(g_hs + (size_t)t * BATCH * HSZ);
            dst[((m0 + rl0) * HSZ + colb) >> 1]     = __floats2half2_rn(hv[0], hv[1]);
            dst[((m0 + rl0 + 8) * HSZ + colb) >> 1] = __floats2half2_rn(hv[2], hv[3]);
        }
        // epilogue A: h1(t+1), c1
        if (t + 1 < TSTEPS) {
            float hv[4];
#pragma unroll
            for (int j = 0; j < 4; j++) {
                int cl = 2 * tq + (j & 1);
                float p[4];
#pragma unroll
                for (int s = 0; s < 4; s++) p[s] = accA[s][j] + b0s[s * 8 + cl];
                float ig = sig_ap(p[0]), fg = sig_ap(p[1]);
                float gg = tanh_ap(p[2]), og = sig_ap(p[3]);
                float c = fg * c1v[j] + ig * gg;
                c1v[j] = c;
                hv[j] = og * tanh_ap(c);
            }
            __half2* dst = (__half2*)(g_h1[(t + 1) & 1]);
            dst[((m0 + rl0) * HSZ + colb) >> 1]     = __floats2half2_rn(hv[0], hv[1]);
            dst[((m0 + rl0 + 8) * HSZ + colb) >> 1] = __floats2half2_rn(hv[2], hv[3]);
        }
        grp_barrier(grp);
    }
}

// ---------------- advantage head: M=64 tiles, warps split over chunk-halves ----------------
__global__ void __launch_bounds__(256) k_head(const float* __restrict__ advb1,
                                              const float* __restrict__ advw2) {
    extern __shared__ char smraw[];
    __half* At  = (__half*)smraw;               // 64 x PAH
    __half* Wc  = At + 64 * PAH;                // 64 x PAH (two 32-row chunk blocks)
    float*  b1s = (float*)(Wc + 64 * PAH);      // 256
    float*  w2s = b1s + HSZ;                    // 256
    float*  part = w2s + HSZ;                   // 2 x 64

    int tid = threadIdx.x;
    size_t rowbase = (size_t)blockIdx.x * 64;

    for (int i = tid; i < 64 * 32; i += 256) {
        int r = i >> 5, c = (i & 31) * 8;
        *(uint4*)(At + r * PAH + c) = *(const uint4*)(g_hs + rowbase * HSZ + r * HSZ + c);
    }
    if (tid < HSZ) { b1s[tid] = advb1[tid]; w2s[tid] = advw2[tid]; }

    int w = tid >> 5, lane = tid & 31, g = lane >> 2, tq = lane & 3;
    int quad = lane >> 3, qi = lane & 7;
    int wm = w & 3;        // row band: rows wm*16..+15
    int wh = w >> 2;       // chunk half: 0 -> chunks 0..3, 1 -> chunks 4..7
    uint32_t a_off = ((uint32_t)(wm * 16 + (quad & 1) * 8 + qi) * PAH + (quad >> 1) * 8) * 2;
    uint32_t at_s = (uint32_t)__cvta_generic_to_shared(At);
    uint32_t b_off = ((uint32_t)((quad >> 1) * 8 + qi) * PAH + (quad & 1) * 8) * 2;
    uint32_t wc_s = (uint32_t)__cvta_generic_to_shared(Wc) + b_off + (uint32_t)wh * 32 * PAH * 2;
    const uint32_t PSTRIDE = 16 * PAH * 2;

    float ps0 = 0.f, ps1 = 0.f;

    for (int it = 0; it < 4; it++) {
        __syncthreads();
        // stage 2 chunks: Wc rows 0..31 <- chunk it, rows 32..63 <- chunk it+4
        for (int i = tid; i < 64 * 32; i += 256) {
            int r = i >> 5, c = (i & 31) * 8;
            int arow = (r < 32) ? (it * 32 + r) : ((it + 4) * 32 + r - 32);
            *(uint4*)(Wc + r * PAH + c) = *(const uint4*)(g_advw1 + arow * HSZ + c);
        }
        __syncthreads();
        float acc[4][4] = {};
#pragma unroll
        for (int kc = 0; kc < HSZ; kc += 16) {
            uint32_t a0, a1, a2, a3, b0, b1, b2, b3;
            ldsm_x4(a0, a1, a2, a3, at_s + a_off + kc * 2);
#pragma unroll
            for (int p = 0; p < 2; p++) {
                ldsm_x4(b0, b1, b2, b3, wc_s + p * PSTRIDE + kc * 2);
                mma16816(acc[2 * p],     a0, a1, a2, a3, b0, b1);
                mma16816(acc[2 * p + 1], a0, a1, a2, a3, b2, b3);
            }
        }
        int c0 = (it + wh * 4) * 32;
#pragma unroll
        for (int nt = 0; nt < 4; nt++) {
#pragma unroll
            for (int j = 0; j < 4; j++) {
                int col = c0 + nt * 8 + 2 * tq + (j & 1);
                float v = acc[nt][j] + b1s[col];
                v = fmaxf(v, 0.f) * w2s[col];
                if (j & 2) ps1 += v; else ps0 += v;
            }
        }
    }
    ps0 += __shfl_xor_sync(0xffffffffu, ps0, 1);
    ps0 += __shfl_xor_sync(0xffffffffu, ps0, 2);
    ps1 += __shfl_xor_sync(0xffffffffu, ps1, 1);
    ps1 += __shfl_xor_sync(0xffffffffu, ps1, 2);
    if (tq == 0) {
        part[wh * 64 + wm * 16 + g]     = ps0;
        part[wh * 64 + wm * 16 + g + 8] = ps1;
    }
    __syncthreads();
    if (tid < 64)
        g_scores[rowbase + tid] = part[tid] + part[64 + tid];   // +b2 omitted: softmax-invariant
}

// ---------------- softmax over contiguous 1024-blocks ----------------
__global__ void __launch_bounds__(256) k_softmax(float* __restrict__ out) {
    __shared__ float red[256];
    int row = blockIdx.x, tid = threadIdx.x;
    const float* src = g_scores + row * 1024;

    float m = -1e30f;
    for (int j = tid; j < 1024; j += 256) m = fmaxf(m, src[j]);
    red[tid] = m; __syncthreads();
    for (int s = 128; s > 0; s >>= 1) { if (tid < s) red[tid] = fmaxf(red[tid], red[tid + s]); __syncthreads(); }
    m = red[0]; __syncthreads();

    float sum = 0.f;
    float e[4];
#pragma unroll
    for (int k = 0; k < 4; k++) { e[k] = expf(src[tid + k * 256] - m); sum += e[k]; }
    red[tid] = sum; __syncthreads();
    for (int s = 128; s > 0; s >>= 1) { if (tid < s) red[tid] += red[tid + s]; __syncthreads(); }
    float inv = 1.f / red[0];
#pragma unroll
    for (int k = 0; k < 4; k++) out[row * 1024 + tid + k * 256] = e[k] * inv;
}

// ---------------- launch ----------------
extern "C" void kernel_launch(void* const* d_in, const int* in_sizes, int n_in,
                              void* d_out, int out_size) {
    (void)in_sizes; (void)n_in; (void)out_size;
    const float* x     = (const float*)d_in[0];
    const float* wih0  = (const float*)d_in[1];
    const float* whh0  = (const float*)d_in[2];
    const float* bih0  = (const float*)d_in[3];
    const float* bhh0  = (const float*)d_in[4];
    const float* wih1  = (const float*)d_in[5];
    const float* whh1  = (const float*)d_in[6];
    const float* bih1  = (const float*)d_in[7];
    const float* bhh1  = (const float*)d_in[8];
    const float* advw1 = (const float*)d_in[9];
    const float* advb1 = (const float*)d_in[10];
    const float* advw2 = (const float*)d_in[11];
    float* out = (float*)d_out;

    const int SMM = (2 * 128 + 3 * 32) * PA * 2 + 128 * 16 * 2 + (32 * FIN + 64) * 4;
    const int SMH = 128 * PAH * 2 + (2 * HSZ + 128) * 4;
    cudaFuncSetAttribute(k_main, cudaFuncAttributeMaxDynamicSharedMemorySize, SMM);
    cudaFuncSetAttribute(k_head, cudaFuncAttributeMaxDynamicSharedMemorySize, SMH);

    k_prep<<<1024, 256>>>(whh0, wih1, whh1, advw1, bih0, bhh0, bih1, bhh1);
    k_xpose<<<2048, 256>>>(x);
    k_main<<<NB, 256, SMM>>>(wih0);
    k_head<<<8192, 256, SMH>>>(advb1, advw2);
    k_softmax<<<512, 256>>>(out);
}